// round 4
// baseline (speedup 1.0000x reference)
#include <cuda_runtime.h>
#include <cstdint>
#include <cstddef>

#define SEQLEN 512
#define BATCH  64
#define HID    512
#define INP    512
#define G4     2048
#define NB_REC 128
#define NT_REC 256

// ---------------- device scratch ----------------
__device__ float g_xproj[(size_t)SEQLEN * BATCH * G4];
__device__ float g_hbuf[2][BATCH * HID];
__device__ int   g_flags[4][32];

// ---------------- helpers ----------------
__device__ __forceinline__ void fma2(unsigned long long& d, unsigned long long a,
                                     unsigned long long b) {
    asm("fma.rn.f32x2 %0, %1, %2, %0;" : "+l"(d) : "l"(a), "l"(b));
}
__device__ __forceinline__ float f2sum(unsigned long long v) {
    float lo, hi;
    asm("mov.b64 {%0, %1}, %2;" : "=f"(lo), "=f"(hi) : "l"(v));
    return lo + hi;
}
__device__ __forceinline__ float sigf(float x) { return 1.0f / (1.0f + __expf(-x)); }
__device__ __forceinline__ float tanhf_acc(float x) {
    return 2.0f / (1.0f + __expf(-2.0f * x)) - 1.0f;
}
__device__ __forceinline__ unsigned smem_u32(const void* p) {
    unsigned a;
    asm("{ .reg .u64 t; cvta.to.shared.u64 t, %1; cvt.u32.u64 %0, t; }" : "=r"(a) : "l"(p));
    return a;
}
__device__ __forceinline__ void cp16(unsigned dst, const void* src) {
    asm volatile("cp.async.cg.shared.global [%0], [%1], 16;" :: "r"(dst), "l"(src));
}
__device__ __forceinline__ unsigned long long lds64(unsigned addr) {
    unsigned long long v;
    asm("ld.shared.b64 %0, [%1];" : "=l"(v) : "r"(addr));
    return v;
}
__device__ __forceinline__ int ld_acq(const int* p) {
    int v;
    asm volatile("ld.acquire.gpu.global.s32 %0, [%1];" : "=r"(v) : "l"(p) : "memory");
    return v;
}
__device__ __forceinline__ void st_rel(int* p, int v) {
    asm volatile("st.release.gpu.global.s32 [%0], %1;" :: "l"(p), "r"(v) : "memory");
}

__global__ void init_flags() {
    if (threadIdx.x < 128) ((int*)g_flags)[threadIdx.x] = 0;
}

// =====================================================================================
// Kernel 1: x_proj = input @ W_ih^T + (b_ih + b_hh).  M=32768, N=2048, K=512.
// Block 128x128, 256 threads, thread tile 8x8, k-stage 32, cp.async double buffer.
// Flat 16KB tiles with 16B-chunk XOR swizzle (conflict-light, zero padding).
// =====================================================================================
__global__ __launch_bounds__(256, 1)
void gemm_xproj(const float* __restrict__ A, const float* __restrict__ W,
                const float* __restrict__ bih, const float* __restrict__ bhh)
{
    extern __shared__ char sm[];
    const unsigned SB = smem_u32(sm);
    const int tid = threadIdx.x;
    const int tm  = tid >> 4;      // 0..15 -> M rows tm*8..+8
    const int tn  = tid & 15;      // 0..15 -> N cols {tn + 16j}
    const int n0  = blockIdx.x * 128;
    const int m0  = blockIdx.y * 128;

    auto copy_tile = [&](int kt) {
        const unsigned bb = SB + (unsigned)(kt & 1) * 32768u;
        const int k0 = kt * 32;
        #pragma unroll
        for (int u = 0; u < 4; u++) {           // A: 128 rows x 8 chunks of 16B
            int q = tid + u * 256;
            int r = q >> 3, c = q & 7;
            unsigned sw = (unsigned)((c ^ ((r & 15) >> 1)) << 4);
            cp16(bb + (unsigned)(r << 7) + sw, &A[(size_t)(m0 + r) * INP + k0 + c * 4]);
        }
        #pragma unroll
        for (int u = 0; u < 4; u++) {           // B: 128 n-rows x 8 chunks
            int q = tid + u * 256;
            int r = q >> 3, c = q & 7;
            unsigned sw = (unsigned)((c ^ ((r & 15) >> 1)) << 4);
            cp16(bb + 16384u + (unsigned)(r << 7) + sw,
                 &W[(size_t)(n0 + r) * INP + k0 + c * 4]);
        }
        asm volatile("cp.async.commit_group;");
    };

    unsigned long long acc[8][8];
    #pragma unroll
    for (int i = 0; i < 8; i++)
        #pragma unroll
        for (int j = 0; j < 8; j++) acc[i][j] = 0ull;

    copy_tile(0);
    copy_tile(1);

    for (int kt = 0; kt < 16; kt++) {
        if (kt < 14) asm volatile("cp.async.wait_group 1;" ::: "memory");
        else         asm volatile("cp.async.wait_group 0;" ::: "memory");
        __syncthreads();

        const unsigned ab = SB + (unsigned)(kt & 1) * 32768u;
        const unsigned wb = ab + 16384u;
        #pragma unroll
        for (int kp = 0; kp < 16; kp++) {
            unsigned long long av[8], bv[8];
            #pragma unroll
            for (int i = 0; i < 8; i++) {
                int r = tm * 8 + i;
                av[i] = lds64(ab + (unsigned)(r << 7)
                                 + (unsigned)((kp ^ (r & 14)) << 3));
            }
            #pragma unroll
            for (int j = 0; j < 8; j++) {
                int n = tn + 16 * j;
                bv[j] = lds64(wb + (unsigned)(n << 7)
                                 + (unsigned)((kp ^ (tn & 14)) << 3));
            }
            #pragma unroll
            for (int i = 0; i < 8; i++)
                #pragma unroll
                for (int j = 0; j < 8; j++) fma2(acc[i][j], av[i], bv[j]);
        }
        __syncthreads();
        if (kt + 2 < 16) copy_tile(kt + 2);
    }

    #pragma unroll
    for (int j = 0; j < 8; j++) {
        int n = n0 + tn + 16 * j;
        float bias = bih[n] + bhh[n];
        #pragma unroll
        for (int i = 0; i < 8; i++)
            g_xproj[(size_t)(m0 + tm * 8 + i) * G4 + n] = f2sum(acc[i][j]) + bias;
    }
}

// =====================================================================================
// Kernel 2: persistent recurrence. 128 blocks = 4 bi x 32 cj; block = 16b x 64g x 512k.
// 256 threads; lane = (s, pb, pg); ksub = warp*2+s -> 16 k-subranges of 32k.
// Thread tile 8b x 8g over 32k (1.0 B/FMA). W in smem with 8B-granule XOR swizzle.
// Release/acquire flag barrier, cell state in register, xproj prefetch.
// =====================================================================================
#define RS_W   0u
#define RS_H   131072u
#define RS_RED 163840u
#define RED_S  1028          // floats per ks slab
#define RS_TOTAL 229632

__global__ __launch_bounds__(NT_REC, 1)
void lstm_rec(const float* __restrict__ h0, const float* __restrict__ c0,
              const float* __restrict__ Whh, float* __restrict__ out, int write_hc)
{
    extern __shared__ char sm[];
    const unsigned SB = smem_u32(sm);
    const int tid  = threadIdx.x;
    const int bi   = blockIdx.x >> 5;   // 0..3
    const int cj   = blockIdx.x & 31;   // 0..31
    const int lane = tid & 31;
    const int w    = tid >> 5;          // 0..7
    const int pg   = lane & 7;          // gate-row group (8 rows)
    const int pb   = (lane >> 3) & 1;   // batch half (8 rows)
    const int s    = lane >> 4;         // k half within warp
    const int ksub = w * 2 + s;         // 0..15, k range ksub*32..+32

    const int cb   = tid >> 4;          // phase-C batch row 0..15
    const int ccol = tid & 15;          // phase-C hidden col 0..15
    const size_t hofs = (size_t)(bi * 16 + cb) * HID + cj * 16 + ccol;

    // ---- resident W_hh slice: 64 rows (r = ty*16+jc) x 512 k, granule-swizzled ----
    for (int idx = tid; idx < 64 * 256; idx += NT_REC) {
        int r = idx >> 8;               // 0..63
        int g = idx & 255;              // 8B granule
        int ty = r >> 4, jc = r & 15;
        int pgr = r >> 3;
        float2 v = *(const float2*)&Whh[(size_t)(ty * HID + cj * 16 + jc) * HID + g * 2];
        *(float2*)(sm + RS_W + (unsigned)(r << 11) + (unsigned)((g ^ (pgr << 1)) << 3)) = v;
    }
    float creg = c0[hofs];
    __syncthreads();

    float* red = (float*)(sm + RS_RED);
    const unsigned pgx = (unsigned)(pg << 4);
    unsigned wbase[8], hbase[8];
    #pragma unroll
    for (int ig = 0; ig < 8; ig++)
        wbase[ig] = SB + RS_W + (unsigned)((pg * 8 + ig) << 11) + (unsigned)(ksub << 7);
    #pragma unroll
    for (int ib = 0; ib < 8; ib++)
        hbase[ib] = SB + RS_H + (unsigned)((pb * 8 + ib) << 11) + (unsigned)(ksub << 7);

    int* flags = &g_flags[bi][0];

    for (int t = 0; t < SEQLEN; t++) {
        // prefetch x_proj gates (no dependence on h_t)
        size_t xofs = ((size_t)t * BATCH + bi * 16 + cb) * G4 + cj * 16 + ccol;
        float xg0 = __ldcg(&g_xproj[xofs]);
        float xg1 = __ldcg(&g_xproj[xofs + HID]);
        float xg2 = __ldcg(&g_xproj[xofs + 2 * HID]);
        float xg3 = __ldcg(&g_xproj[xofs + 3 * HID]);

        // wait for all 32 producers of this bi group
        if (t > 0 && tid < 32) { while (ld_acq(&flags[tid]) < t) { } }
        __syncthreads();

        // stage h_t (16 x 512 floats, flat)
        const float* hsrc = (t == 0) ? h0 : g_hbuf[t & 1];
        const float* hrow = hsrc + (size_t)(bi * 16) * HID;
        #pragma unroll
        for (int u = 0; u < 16; u++) {
            int idx = tid + u * NT_REC;
            int b = idx >> 8, g = idx & 255;
            float2 v = __ldcg((const float2*)(hrow + (size_t)b * HID + g * 2));
            *(float2*)(sm + RS_H + (unsigned)(b << 11) + (unsigned)(g << 3)) = v;
        }
        __syncthreads();

        // phase B: 8b x 8g partial gates over 32 k
        unsigned long long acc[8][8];
        #pragma unroll
        for (int ib = 0; ib < 8; ib++)
            #pragma unroll
            for (int ig = 0; ig < 8; ig++) acc[ib][ig] = 0ull;

        #pragma unroll
        for (int kp = 0; kp < 16; kp++) {
            const unsigned koff = ((unsigned)(kp << 3)) ^ pgx;
            unsigned long long wv[8];
            #pragma unroll
            for (int ig = 0; ig < 8; ig++) wv[ig] = lds64(wbase[ig] + koff);
            #pragma unroll
            for (int ib = 0; ib < 8; ib++) {
                unsigned long long hv = lds64(hbase[ib] + (unsigned)(kp << 3));
                #pragma unroll
                for (int ig = 0; ig < 8; ig++) fma2(acc[ib][ig], hv, wv[ig]);
            }
        }

        // write partials: red[ksub][b][grow]
        #pragma unroll
        for (int ib = 0; ib < 8; ib++) {
            float4 v0, v1;
            v0.x = f2sum(acc[ib][0]); v0.y = f2sum(acc[ib][1]);
            v0.z = f2sum(acc[ib][2]); v0.w = f2sum(acc[ib][3]);
            v1.x = f2sum(acc[ib][4]); v1.y = f2sum(acc[ib][5]);
            v1.z = f2sum(acc[ib][6]); v1.w = f2sum(acc[ib][7]);
            float* dst = red + ksub * RED_S + (pb * 8 + ib) * 64 + pg * 8;
            *(float4*)dst = v0;
            *(float4*)(dst + 4) = v1;
        }
        __syncthreads();

        // phase C: reduce 16 ksubs, 4 gate types; one cell per thread
        float s0 = 0.f, s1 = 0.f, s2 = 0.f, s3 = 0.f;
        #pragma unroll
        for (int ks = 0; ks < 16; ks++) {
            const float* rp = red + ks * RED_S + cb * 64 + ccol;
            s0 += rp[0]; s1 += rp[16]; s2 += rp[32]; s3 += rp[48];
        }
        float iv = sigf(s0 + xg0);
        float fv = sigf(s1 + xg1);
        float gv = tanhf_acc(s2 + xg2);
        float ov = sigf(s3 + xg3);
        creg = fv * creg + iv * gv;
        float hn = ov * tanhf_acc(creg);

        g_hbuf[(t + 1) & 1][hofs] = hn;
        out[(size_t)t * (BATCH * HID) + hofs] = hn;
        if (write_hc && t == SEQLEN - 1) {
            out[(size_t)SEQLEN * BATCH * HID + hofs] = hn;
            out[(size_t)SEQLEN * BATCH * HID + BATCH * HID + hofs] = creg;
        }

        __syncthreads();
        if (tid == 0) st_rel(&g_flags[bi][cj], t + 1);
    }
}

// =====================================================================================
extern "C" void kernel_launch(void* const* d_in, const int* in_sizes, int n_in,
                              void* d_out, int out_size)
{
    const float* input = (const float*)d_in[0];
    const float* h0    = (const float*)d_in[1];
    const float* c0    = (const float*)d_in[2];
    const float* Wih   = (const float*)d_in[3];
    const float* Whh   = (const float*)d_in[4];
    const float* bih   = (const float*)d_in[5];
    const float* bhh   = (const float*)d_in[6];
    (void)in_sizes; (void)n_in;

    float* out = (float*)d_out;
    const int n_outputs = SEQLEN * BATCH * HID;
    int write_hc = (out_size >= n_outputs + 2 * BATCH * HID) ? 1 : 0;

    static int configured = 0;
    if (!configured) {
        cudaFuncSetAttribute(gemm_xproj, cudaFuncAttributeMaxDynamicSharedMemorySize,
                             65536);
        cudaFuncSetAttribute(lstm_rec, cudaFuncAttributeMaxDynamicSharedMemorySize,
                             RS_TOTAL);
        configured = 1;
    }

    init_flags<<<1, 128>>>();
    gemm_xproj<<<dim3(G4 / 128, (SEQLEN * BATCH) / 128), 256, 65536>>>(
        input, Wih, bih, bhh);
    lstm_rec<<<NB_REC, NT_REC, RS_TOTAL>>>(h0, c0, Whh, out, write_hc);
}

// round 6
// speedup vs baseline: 1.2028x; 1.2028x over previous
#include <cuda_runtime.h>
#include <cstdint>
#include <cstddef>

#define SEQLEN 512
#define BATCH  64
#define HID    512
#define INP    512
#define G4     2048
#define NB_REC 128
#define NT_REC 512

// ---------------- device scratch ----------------
__device__ float g_xproj[(size_t)SEQLEN * BATCH * G4];
__device__ __align__(16) float g_hbuf[2][BATCH * HID];
__device__ int   g_flags[4][32];

// ---------------- packed fp32x2 FMA ----------------
__device__ __forceinline__ void fma2(unsigned long long& d, unsigned long long a,
                                     unsigned long long b) {
    asm("fma.rn.f32x2 %0, %1, %2, %0;" : "+l"(d) : "l"(a), "l"(b));
}
__device__ __forceinline__ float f2sum(unsigned long long v) {
    float lo, hi;
    asm("mov.b64 {%0, %1}, %2;" : "=f"(lo), "=f"(hi) : "l"(v));
    return lo + hi;
}
__device__ __forceinline__ float sigf(float x) { return 1.0f / (1.0f + __expf(-x)); }
__device__ __forceinline__ float tanhf_acc(float x) {
    return 2.0f / (1.0f + __expf(-2.0f * x)) - 1.0f;
}
__device__ __forceinline__ unsigned smem_u32(const void* p) {
    unsigned a;
    asm("{ .reg .u64 t; cvta.to.shared.u64 t, %1; cvt.u32.u64 %0, t; }" : "=r"(a) : "l"(p));
    return a;
}
__device__ __forceinline__ void cp16(unsigned dst, const void* src) {
    asm volatile("cp.async.cg.shared.global [%0], [%1], 16;" :: "r"(dst), "l"(src));
}

__global__ void init_flags() {
    if (threadIdx.x < 128) ((int*)g_flags)[threadIdx.x] = 0;
}

// =====================================================================================
// Kernel 1: x_proj = input @ W_ih^T + (b_ih + b_hh)  — EXACT round-2 version (known good)
// =====================================================================================
#define ASTRIDE 36
#define ASZ (128 * ASTRIDE)
#define BSZ (64 * ASTRIDE)

__global__ __launch_bounds__(256, 2)
void gemm_xproj(const float* __restrict__ A, const float* __restrict__ W,
                const float* __restrict__ bih, const float* __restrict__ bhh)
{
    extern __shared__ float smem[];
    float* Asm[2] = { smem,       smem + (ASZ + BSZ) };
    float* Bsm[2] = { smem + ASZ, smem + (ASZ + BSZ) + ASZ };

    const int tid = threadIdx.x;
    const int tm  = tid >> 4;
    const int tn  = tid & 15;
    const int m0  = blockIdx.x * 128;
    const int n0  = blockIdx.y * 64;

    auto copy_tile = [&](int kt, int sel) {
        const int k0 = kt * 32;
        unsigned abase = smem_u32(Asm[sel]);
        unsigned bbase = smem_u32(Bsm[sel]);
        #pragma unroll
        for (int i = 0; i < 4; i++) {
            int idx = tid + i * 256;
            int r = idx >> 3, c = (idx & 7) * 4;
            cp16(abase + (r * ASTRIDE + c) * 4, &A[(size_t)(m0 + r) * INP + k0 + c]);
        }
        #pragma unroll
        for (int i = 0; i < 2; i++) {
            int idx = tid + i * 256;
            int r = idx >> 3, c = (idx & 7) * 4;
            cp16(bbase + (r * ASTRIDE + c) * 4, &W[(size_t)(n0 + r) * INP + k0 + c]);
        }
        asm volatile("cp.async.commit_group;");
    };

    unsigned long long acc[8][4];
    #pragma unroll
    for (int i = 0; i < 8; i++)
        #pragma unroll
        for (int j = 0; j < 4; j++) acc[i][j] = 0ull;

    copy_tile(0, 0);

    for (int kt = 0; kt < INP / 32; kt++) {
        asm volatile("cp.async.wait_group 0;");
        __syncthreads();
        if (kt + 1 < INP / 32) copy_tile(kt + 1, (kt + 1) & 1);

        const float* As = Asm[kt & 1];
        const float* Bs = Bsm[kt & 1];
        #pragma unroll
        for (int kp = 0; kp < 16; kp++) {
            unsigned long long av[8], bv[4];
            #pragma unroll
            for (int i = 0; i < 8; i++)
                av[i] = *(const unsigned long long*)&As[(tm * 8 + i) * ASTRIDE + kp * 2];
            #pragma unroll
            for (int j = 0; j < 4; j++)
                bv[j] = *(const unsigned long long*)&Bs[(tn + j * 16) * ASTRIDE + kp * 2];
            #pragma unroll
            for (int i = 0; i < 8; i++)
                #pragma unroll
                for (int j = 0; j < 4; j++) fma2(acc[i][j], av[i], bv[j]);
        }
        __syncthreads();
    }

    #pragma unroll
    for (int j = 0; j < 4; j++) {
        int n = n0 + tn + j * 16;
        float bias = bih[n] + bhh[n];
        #pragma unroll
        for (int i = 0; i < 8; i++)
            g_xproj[(size_t)(m0 + tm * 8 + i) * G4 + n] = f2sum(acc[i][j]) + bias;
    }
}

// =====================================================================================
// Kernel 2: persistent recurrence — 512 threads (16 k-groups of 32k).
// red row stride 66 floats (8B-aligned only) => ALL red accesses are float2.
// =====================================================================================
struct RecSmem {
    float Wsm[64][514];       // 131584 B
    float hs[16][516];        //  33024 B
    float red[16][16][66];    //  67584 B   => 232192 B total (fits 227KB+carve)
};

__global__ __launch_bounds__(NT_REC, 1)
void lstm_rec(const float* __restrict__ h0, const float* __restrict__ c0,
              const float* __restrict__ Whh, float* __restrict__ out, int write_hc)
{
    extern __shared__ char smem_raw[];
    RecSmem* sm = (RecSmem*)smem_raw;

    const int tid  = threadIdx.x;
    const int bi   = blockIdx.x >> 5;
    const int cj   = blockIdx.x & 31;
    const int lane = tid & 31;
    const int kg   = tid >> 5;          // 0..15 warp = 32-k group (16 kp)
    const int jl   = lane & 15;
    const int b0   = (lane >> 4) * 8;

    const int cb  = (tid & 255) >> 4;
    const int cjl = tid & 15;
    const size_t hofs = (size_t)(bi * 16 + cb) * HID + cj * 16 + cjl;

    for (int i = tid; i < 64 * 256; i += NT_REC) {
        int r = i >> 8;
        int kp2 = (i & 255) * 2;
        int ty = r >> 4, j = r & 15;
        *(float2*)&sm->Wsm[r][kp2] =
            *(const float2*)&Whh[(size_t)(ty * HID + cj * 16 + j) * HID + kp2];
    }
    float creg = (tid < 256) ? c0[hofs] : 0.0f;
    __syncthreads();

    volatile int* flags = (volatile int*)&g_flags[bi][0];

    for (int t = 0; t < SEQLEN; t++) {
        float xg0 = 0.f, xg1 = 0.f, xg2 = 0.f, xg3 = 0.f;
        if (tid < 256) {
            size_t xofs = ((size_t)t * BATCH + bi * 16 + cb) * G4 + cj * 16 + cjl;
            xg0 = __ldcg(&g_xproj[xofs]);
            xg1 = __ldcg(&g_xproj[xofs + HID]);
            xg2 = __ldcg(&g_xproj[xofs + 2 * HID]);
            xg3 = __ldcg(&g_xproj[xofs + 3 * HID]);
        }

        if (t > 0) {
            if (tid < 32) { while (flags[tid] < t) { } }
            __threadfence();
        }
        __syncthreads();

        const float* hsrc = (t == 0) ? h0 : g_hbuf[t & 1];
        const float* hrow = hsrc + (size_t)(bi * 16) * HID;
        #pragma unroll
        for (int u = 0; u < 4; u++) {
            int i = tid + u * NT_REC;
            int b = i >> 7;
            int c4 = (i & 127) * 4;
            float4 v = __ldcg((const float4*)(hrow + (size_t)b * HID + c4));
            *(float4*)&sm->hs[b][c4] = v;
        }
        __syncthreads();

        unsigned long long acc[8][4];
        #pragma unroll
        for (int i = 0; i < 8; i++)
            #pragma unroll
            for (int j = 0; j < 4; j++) acc[i][j] = 0ull;

        const int kp0 = kg * 16;
        #pragma unroll
        for (int kp = kp0; kp < kp0 + 16; kp++) {
            unsigned long long wv[4], hv[8];
            #pragma unroll
            for (int ty = 0; ty < 4; ty++)
                wv[ty] = *(const unsigned long long*)&sm->Wsm[ty * 16 + jl][kp * 2];
            #pragma unroll
            for (int i = 0; i < 8; i++)
                hv[i] = *(const unsigned long long*)&sm->hs[b0 + i][kp * 2];
            #pragma unroll
            for (int i = 0; i < 8; i++)
                #pragma unroll
                for (int ty = 0; ty < 4; ty++) fma2(acc[i][ty], hv[i], wv[ty]);
        }
        // write partials (float2 pairs: stride-66 rows are only 8B-aligned)
        #pragma unroll
        for (int i = 0; i < 8; i++) {
            float2 v0, v1;
            v0.x = f2sum(acc[i][0]); v0.y = f2sum(acc[i][1]);
            v1.x = f2sum(acc[i][2]); v1.y = f2sum(acc[i][3]);
            float* dst = &sm->red[kg][jl][(b0 + i) * 4];
            *(float2*)dst = v0;
            *(float2*)(dst + 2) = v1;
        }
        __syncthreads();

        if (tid < 256) {
            float s0, s1, s2, s3;
            {
                const float* rp = &sm->red[0][cjl][cb * 4];
                float2 a = *(const float2*)rp;
                float2 b = *(const float2*)(rp + 2);
                s0 = a.x; s1 = a.y; s2 = b.x; s3 = b.y;
            }
            #pragma unroll
            for (int kk = 1; kk < 16; kk++) {
                const float* rp = &sm->red[kk][cjl][cb * 4];
                float2 a = *(const float2*)rp;
                float2 b = *(const float2*)(rp + 2);
                s0 += a.x; s1 += a.y; s2 += b.x; s3 += b.y;
            }
            float iv = sigf(s0 + xg0);
            float fv = sigf(s1 + xg1);
            float gv = tanhf_acc(s2 + xg2);
            float ov = sigf(s3 + xg3);
            creg = fv * creg + iv * gv;
            float hn = ov * tanhf_acc(creg);

            g_hbuf[(t + 1) & 1][hofs] = hn;
            out[(size_t)t * (BATCH * HID) + hofs] = hn;
            if (write_hc && t == SEQLEN - 1) {
                out[(size_t)SEQLEN * BATCH * HID + hofs] = hn;
                out[(size_t)SEQLEN * BATCH * HID + BATCH * HID + hofs] = creg;
            }
        }

        __threadfence();
        __syncthreads();
        if (tid == 0) atomicExch((int*)&g_flags[bi][cj], t + 1);
    }
}

// =====================================================================================
extern "C" void kernel_launch(void* const* d_in, const int* in_sizes, int n_in,
                              void* d_out, int out_size)
{
    const float* input = (const float*)d_in[0];
    const float* h0    = (const float*)d_in[1];
    const float* c0    = (const float*)d_in[2];
    const float* Wih   = (const float*)d_in[3];
    const float* Whh   = (const float*)d_in[4];
    const float* bih   = (const float*)d_in[5];
    const float* bhh   = (const float*)d_in[6];
    (void)in_sizes; (void)n_in;

    float* out = (float*)d_out;
    const int n_outputs = SEQLEN * BATCH * HID;
    int write_hc = (out_size >= n_outputs + 2 * BATCH * HID) ? 1 : 0;

    static int configured = 0;
    const int gemm_smem = 2 * (ASZ + BSZ) * (int)sizeof(float);
    if (!configured) {
        cudaFuncSetAttribute(gemm_xproj, cudaFuncAttributeMaxDynamicSharedMemorySize,
                             gemm_smem);
        cudaFuncSetAttribute(lstm_rec, cudaFuncAttributeMaxDynamicSharedMemorySize,
                             (int)sizeof(RecSmem));
        configured = 1;
    }

    init_flags<<<1, 128>>>();
    gemm_xproj<<<dim3((SEQLEN * BATCH) / 128, G4 / 64), 256, gemm_smem>>>(
        input, Wih, bih, bhh);
    lstm_rec<<<NB_REC, NT_REC, sizeof(RecSmem)>>>(h0, c0, Whh, out, write_hc);
}